// round 8
// baseline (speedup 1.0000x reference)
#include <cuda_runtime.h>

// SSIM, fused single-pass box filters via per-warp sliding windows.
//
// img (16,3,512,512) f32; channel 0 only, crop 4 -> 504x504 region.
// Four windowed quantities (mu1, mu2, E[x1x2], E[x1^2+x2^2]):
//   vertical 11-row running sums in registers (incremental add/retire),
//   horizontal 11-col window via log-step warp shuffles (5 SHFL each).
// Each warp: 22 output columns x 42 output rows of one image.
// 23 colgroups * 16 images * 12 strips = 4416 warps -> 1104 blocks x 128 thr
// (all CTAs co-resident: ~7.5 warps/SMSP for SHFL latency hiding).

#define IMG_STRIDE (3 * 512 * 512)
#define W_IN 512
#define OUTW 504
#define CROPV 4
#define NCOLG 23          // ceil(504/22)
#define STRIPS 12
#define STRIP_H 42        // 12*42 = 504
#define NWARPS (NCOLG * 16 * STRIPS)        // 4416
#define WARPS_PER_BLOCK 4
#define NBLOCKS (NWARPS / WARPS_PER_BLOCK)  // 1104

__device__ float g_partials[NBLOCKS];

// 11-tap sliding sum across lanes: lane L returns sum of v over lanes L..L+10.
// Valid for lanes 0..21 (consumes up to lane 31).
__device__ __forceinline__ float win11(float v) {
    const unsigned m = 0xffffffffu;
    float s2 = v  + __shfl_down_sync(m, v,  1);   // 2-window
    float s4 = s2 + __shfl_down_sync(m, s2, 2);   // 4-window
    float s8 = s4 + __shfl_down_sync(m, s4, 4);   // 8-window
    float r  = s8 + __shfl_down_sync(m, s2, 8);   // 10-window
    return  r  + __shfl_down_sync(m, v, 10);      // 11-window
}

__global__ __launch_bounds__(128) void ssim_main(
    const float* __restrict__ img1, const float* __restrict__ img2)
{
    const int wib  = threadIdx.x >> 5;
    const int w    = blockIdx.x * WARPS_PER_BLOCK + wib;
    const int lane = threadIdx.x & 31;

    const int g     = w % NCOLG;
    const int t     = w / NCOLG;
    const int img   = t & 15;
    const int strip = t >> 4;

    // This lane's extended column in cropped coords: [22g-5, 22g+26]
    const int col    = g * 22 + lane - 5;
    const bool colok = ((unsigned)col < (unsigned)OUTW);
    const int outc   = g * 22 + lane;
    const bool outok = (lane < 22) && (outc < OUTW);

    const float* p1 = img1 + (long)img * IMG_STRIDE + (col + CROPV);
    const float* p2 = img2 + (long)img * IMG_STRIDE + (col + CROPV);

    const int r0 = strip * STRIP_H;
    int rmin = r0 - 5; if (rmin < 0) rmin = 0;   // first row ever admitted

    float V1 = 0.f, V2 = 0.f, Vss = 0.f, V12 = 0.f;
    float acc = 0.f;

    const float C1 = 6.5025f;      // (0.01*255)^2
    const float C2 = 58.5225f;     // (0.03*255)^2
    const float K  = 1.0f / 121.0f;

    // Prologue: admit rows r0-5 .. r0+4 (zero padding for r < 0).
    #pragma unroll
    for (int k = 0; k < 10; ++k) {
        const int r = r0 - 5 + k;
        float a = 0.f, b = 0.f;
        if (r >= 0 && colok) {
            a = __ldg(p1 + (r + CROPV) * W_IN);
            b = __ldg(p2 + (r + CROPV) * W_IN);
        }
        V1 += a; V2 += b;
        Vss = fmaf(a, a, Vss); Vss = fmaf(b, b, Vss);
        V12 = fmaf(a, b, V12);
    }

    // Main loop over output rows.
    #pragma unroll 2
    for (int y = r0; y < r0 + STRIP_H; ++y) {
        // Retire row y-6 (only if it was ever admitted).
        const int ro = y - 6;
        if (ro >= rmin) {
            float a = 0.f, b = 0.f;
            if (colok) {
                a = __ldg(p1 + (ro + CROPV) * W_IN);   // L1 hit (11-row reuse)
                b = __ldg(p2 + (ro + CROPV) * W_IN);
            }
            V1 -= a; V2 -= b;
            Vss = fmaf(-a, a, Vss); Vss = fmaf(-b, b, Vss);
            V12 = fmaf(-a, b, V12);
        }
        // Admit row y+5 (zero padding beyond 503).
        const int rn = y + 5;
        if (rn < OUTW) {
            float a = 0.f, b = 0.f;
            if (colok) {
                a = __ldg(p1 + (rn + CROPV) * W_IN);
                b = __ldg(p2 + (rn + CROPV) * W_IN);
            }
            V1 += a; V2 += b;
            Vss = fmaf(a, a, Vss); Vss = fmaf(b, b, Vss);
            V12 = fmaf(a, b, V12);
        }

        // Horizontal 11-window across lanes (4 independent shfl chains).
        const float B1  = win11(V1);
        const float B2  = win11(V2);
        const float Bss = win11(Vss);
        const float B12 = win11(V12);

        if (outok) {
            const float mu1  = B1 * K;
            const float mu2  = B2 * K;
            const float mu12 = mu1 * mu2;
            const float musq = fmaf(mu1, mu1, mu2 * mu2);
            const float s12  = fmaf(B12, K, -mu12);   // sigma12
            const float sss  = fmaf(Bss, K, -musq);   // sigma1^2 + sigma2^2
            const float num  = fmaf(2.f, mu12, C1) * fmaf(2.f, s12, C2);
            const float den  = (musq + C1) * (sss + C2);
            acc += __fdividef(num, den);
        }
    }

    // Warp-level reduction, then block-level partial (deterministic).
    #pragma unroll
    for (int d = 16; d; d >>= 1)
        acc += __shfl_xor_sync(0xffffffffu, acc, d);

    __shared__ float sp[WARPS_PER_BLOCK];
    if (lane == 0) sp[wib] = acc;
    __syncthreads();
    if (threadIdx.x == 0) {
        float s = sp[0];
        #pragma unroll
        for (int i = 1; i < WARPS_PER_BLOCK; ++i) s += sp[i];
        g_partials[blockIdx.x] = s;
    }
}

__global__ __launch_bounds__(1024) void ssim_reduce(float* __restrict__ out)
{
    const int tid = threadIdx.x;
    float v = 0.f;
    if (tid < NBLOCKS)        v  = g_partials[tid];
    if (tid + 1024 < NBLOCKS) v += g_partials[tid + 1024];

    #pragma unroll
    for (int d = 16; d; d >>= 1)
        v += __shfl_xor_sync(0xffffffffu, v, d);

    __shared__ float s[32];
    if ((tid & 31) == 0) s[tid >> 5] = v;
    __syncthreads();
    if (tid < 32) {
        float x = s[tid];
        #pragma unroll
        for (int d = 16; d; d >>= 1)
            x += __shfl_xor_sync(0xffffffffu, x, d);
        if (tid == 0)
            out[0] = x * (1.0f / 4064256.0f);   // 16*504*504
    }
}

extern "C" void kernel_launch(void* const* d_in, const int* in_sizes, int n_in,
                              void* d_out, int out_size)
{
    const float* img1 = (const float*)d_in[0];
    const float* img2 = (const float*)d_in[1];
    float* out = (float*)d_out;
    ssim_main<<<NBLOCKS, 128>>>(img1, img2);
    ssim_reduce<<<1, 1024>>>(out);
}

// round 9
// speedup vs baseline: 1.3349x; 1.3349x over previous
#include <cuda_runtime.h>

// SSIM, fused single-pass box filters, 4 columns per lane.
//
// img (16,3,512,512) f32; channel 0, crop 4 -> 504x504.
// Four windowed quantities (B1, B2, Bss=E[x1^2+x2^2]*121, B12):
//   vertical 11-row running sums in registers (incremental add/retire),
//   horizontal 11-col window via local prefix/suffix + 5 independent shfls
//   per quantity producing 4 outputs per lane (118 per warp-row).
// Tiling: 5 colgroups(118) x 16 images x 36 strips(14 rows) = 2880 warps,
// 720 blocks x 128 threads. Final reduction fused via block counter.

#define IMG_STRIDE (3 * 512 * 512)
#define W_IN 512
#define OUTW 504
#define CROPV 4
#define NGROUPS 5
#define GROUP_W 118
#define STRIPS 36
#define STRIP_H 14        // 36*14 = 504
#define NWARPS (NGROUPS * 16 * STRIPS)      // 2880
#define WARPS_PER_BLOCK 4
#define NBLOCKS (NWARPS / WARPS_PER_BLOCK)  // 720

__device__ float g_partials[NBLOCKS];
__device__ int   g_count = 0;

// Horizontal 11-window: lane L holds ext elems m=4L..4L+3 (v0..v3).
// Returns W[k] = sum over ext m'=4L+k .. m'+10, valid for 4L+k <= 117.
__device__ __forceinline__ void win4(float v0, float v1, float v2, float v3,
                                     float& W0, float& W1, float& W2, float& W3)
{
    const unsigned m = 0xffffffffu;
    const float p2 = v0 + v1;
    const float p3 = p2 + v2;
    const float T  = p3 + v3;
    const float suf1 = T - v0;      // v1+v2+v3
    const float suf2 = v2 + v3;
    const float Tn1  = __shfl_down_sync(m, T,  1);
    const float Tn2  = __shfl_down_sync(m, T,  2);
    const float p3n2 = __shfl_down_sync(m, p3, 2);
    const float p1n3 = __shfl_down_sync(m, v0, 3);
    const float p2n3 = __shfl_down_sync(m, p2, 3);
    const float TT = Tn1 + Tn2;
    W0 = T + Tn1 + p3n2;
    W1 = suf1 + TT;
    W2 = (suf2 + p1n3) + TT;
    W3 = (v3 + p2n3) + TT;
}

__global__ __launch_bounds__(128) void ssim_main(
    const float* __restrict__ img1, const float* __restrict__ img2,
    float* __restrict__ out)
{
    const int wib  = threadIdx.x >> 5;
    const int w    = blockIdx.x * WARPS_PER_BLOCK + wib;
    const int lane = threadIdx.x & 31;
    const int tid  = threadIdx.x;

    const int g     = w % NGROUPS;
    const int t     = w / NGROUPS;
    const int img   = t & 15;
    const int strip = t >> 4;

    const int gb = g * GROUP_W;          // first output col of this group
    const int m0 = 4 * lane;             // lane's first ext index

    // Load validity per element k: ext col = gb-5+m0+k must be in [0, 504)
    bool ok[4];
    #pragma unroll
    for (int k = 0; k < 4; ++k) {
        const int ec = gb - 5 + m0 + k;
        ok[k] = ((unsigned)ec < (unsigned)OUTW);
    }
    // Output validity per k
    bool ov[4];
    #pragma unroll
    for (int k = 0; k < 4; ++k) {
        const int mp = m0 + k;
        ov[k] = (mp <= 117) && (gb + mp < OUTW);
    }

    // Base pointers: global col = (ext col) + CROPV = gb - 1 + m0 (+k)
    const float* p1 = img1 + (long)img * IMG_STRIDE + (gb - 1 + m0);
    const float* p2 = img2 + (long)img * IMG_STRIDE + (gb - 1 + m0);

    const int r0 = strip * STRIP_H;
    const int rmin = (r0 - 5 > 0) ? r0 - 5 : 0;   // first row ever admitted

    float V1[4], V2[4], Vss[4], V12[4];
    #pragma unroll
    for (int k = 0; k < 4; ++k) { V1[k] = 0.f; V2[k] = 0.f; Vss[k] = 0.f; V12[k] = 0.f; }
    float acc = 0.f;

    const float C1 = 6.5025f;      // (0.01*255)^2
    const float C2 = 58.5225f;     // (0.03*255)^2
    const float K  = 1.0f / 121.0f;

    // Prologue: admit rows r0-5 .. r0+4 (zero padding for r < 0).
    #pragma unroll
    for (int j = 0; j < 10; ++j) {
        const int r = r0 - 5 + j;
        if (r >= 0) {
            const float* r1 = p1 + (long)(r + CROPV) * W_IN;
            const float* r2 = p2 + (long)(r + CROPV) * W_IN;
            #pragma unroll
            for (int k = 0; k < 4; ++k) {
                const float a = ok[k] ? __ldg(r1 + k) : 0.f;
                const float b = ok[k] ? __ldg(r2 + k) : 0.f;
                V1[k] += a; V2[k] += b;
                Vss[k] = fmaf(a, a, Vss[k]); Vss[k] = fmaf(b, b, Vss[k]);
                V12[k] = fmaf(a, b, V12[k]);
            }
        }
    }

    // Main loop over output rows.
    for (int y = r0; y < r0 + STRIP_H; ++y) {
        // Retire row y-6 (only if it was ever admitted).
        const int ro = y - 6;
        if (ro >= rmin) {
            const float* r1 = p1 + (long)(ro + CROPV) * W_IN;
            const float* r2 = p2 + (long)(ro + CROPV) * W_IN;
            #pragma unroll
            for (int k = 0; k < 4; ++k) {
                const float a = ok[k] ? __ldg(r1 + k) : 0.f;   // L1 hit
                const float b = ok[k] ? __ldg(r2 + k) : 0.f;
                V1[k] -= a; V2[k] -= b;
                Vss[k] = fmaf(-a, a, Vss[k]); Vss[k] = fmaf(-b, b, Vss[k]);
                V12[k] = fmaf(-a, b, V12[k]);
            }
        }
        // Admit row y+5 (zero padding beyond 503).
        const int rn = y + 5;
        if (rn < OUTW) {
            const float* r1 = p1 + (long)(rn + CROPV) * W_IN;
            const float* r2 = p2 + (long)(rn + CROPV) * W_IN;
            #pragma unroll
            for (int k = 0; k < 4; ++k) {
                const float a = ok[k] ? __ldg(r1 + k) : 0.f;
                const float b = ok[k] ? __ldg(r2 + k) : 0.f;
                V1[k] += a; V2[k] += b;
                Vss[k] = fmaf(a, a, Vss[k]); Vss[k] = fmaf(b, b, Vss[k]);
                V12[k] = fmaf(a, b, V12[k]);
            }
        }

        // Horizontal windows (4 quantities, shallow independent shfl chains).
        float B1[4], B2[4], Bss[4], B12[4];
        win4(V1[0],  V1[1],  V1[2],  V1[3],  B1[0],  B1[1],  B1[2],  B1[3]);
        win4(V2[0],  V2[1],  V2[2],  V2[3],  B2[0],  B2[1],  B2[2],  B2[3]);
        win4(Vss[0], Vss[1], Vss[2], Vss[3], Bss[0], Bss[1], Bss[2], Bss[3]);
        win4(V12[0], V12[1], V12[2], V12[3], B12[0], B12[1], B12[2], B12[3]);

        #pragma unroll
        for (int k = 0; k < 4; ++k) {
            if (ov[k]) {
                const float mu1  = B1[k] * K;
                const float mu2  = B2[k] * K;
                const float mu12 = mu1 * mu2;
                const float musq = fmaf(mu1, mu1, mu2 * mu2);
                const float s12  = fmaf(B12[k], K, -mu12);   // sigma12
                const float sss  = fmaf(Bss[k], K, -musq);   // sigma1^2+sigma2^2
                const float num  = fmaf(2.f, mu12, C1) * fmaf(2.f, s12, C2);
                const float den  = (musq + C1) * (sss + C2);
                acc += __fdividef(num, den);
            }
        }
    }

    // ---- block partial + fused final reduction ----
    #pragma unroll
    for (int d = 16; d; d >>= 1)
        acc += __shfl_xor_sync(0xffffffffu, acc, d);

    __shared__ float sp[WARPS_PER_BLOCK];
    __shared__ int   isLast;
    if (lane == 0) sp[wib] = acc;
    __syncthreads();
    if (tid == 0) {
        float s = sp[0] + sp[1] + sp[2] + sp[3];
        g_partials[blockIdx.x] = s;
        __threadfence();
        const int c = atomicAdd(&g_count, 1);
        isLast = (c == NBLOCKS - 1);
    }
    __syncthreads();

    if (isLast) {
        // Deterministic: fixed index order per thread, fixed tree reduce.
        float v = 0.f;
        for (int i = tid; i < NBLOCKS; i += 128)
            v += __ldcg(&g_partials[i]);
        #pragma unroll
        for (int d = 16; d; d >>= 1)
            v += __shfl_xor_sync(0xffffffffu, v, d);
        if (lane == 0) sp[wib] = v;
        __syncthreads();
        if (tid == 0) {
            const float total = sp[0] + sp[1] + sp[2] + sp[3];
            out[0] = total * (1.0f / 4064256.0f);   // 16*504*504
            g_count = 0;                             // reset for next replay
        }
    }
}

extern "C" void kernel_launch(void* const* d_in, const int* in_sizes, int n_in,
                              void* d_out, int out_size)
{
    const float* img1 = (const float*)d_in[0];
    const float* img2 = (const float*)d_in[1];
    float* out = (float*)d_out;
    ssim_main<<<NBLOCKS, 128>>>(img1, img2, out);
}

// round 10
// speedup vs baseline: 1.3957x; 1.0455x over previous
#include <cuda_runtime.h>

// SSIM, fused single-pass box filters, 4 columns per lane.
//
// img (16,3,512,512) f32; channel 0, crop 4 -> 504x504.
// Four windowed quantities (B1, B2, Bss=E[x1^2+x2^2]*121, B12):
//   vertical 11-row running sums in registers (incremental add/retire),
//   horizontal 11-col window via local prefix/suffix + 5 independent shfls
//   per quantity producing 4 outputs per lane (118 per warp-row).
// Tiling: 5 colgroups(118) x 16 images x 36 strips(14 rows) = 2880 warps,
// 720 blocks x 128 threads. Final reduction fused via block counter.

#define IMG_STRIDE (3 * 512 * 512)
#define W_IN 512
#define OUTW 504
#define CROPV 4
#define NGROUPS 5
#define GROUP_W 118
#define STRIPS 36
#define STRIP_H 14        // 36*14 = 504
#define NWARPS (NGROUPS * 16 * STRIPS)      // 2880
#define WARPS_PER_BLOCK 4
#define NBLOCKS (NWARPS / WARPS_PER_BLOCK)  // 720

__device__ float g_partials[NBLOCKS];
__device__ int   g_count = 0;

// Horizontal 11-window: lane L holds ext elems m=4L..4L+3 (v0..v3).
// Returns W[k] = sum over ext m'=4L+k .. m'+10, valid for 4L+k <= 117.
__device__ __forceinline__ void win4(float v0, float v1, float v2, float v3,
                                     float& W0, float& W1, float& W2, float& W3)
{
    const unsigned m = 0xffffffffu;
    const float p2 = v0 + v1;
    const float p3 = p2 + v2;
    const float T  = p3 + v3;
    const float suf1 = T - v0;      // v1+v2+v3
    const float suf2 = v2 + v3;
    const float Tn1  = __shfl_down_sync(m, T,  1);
    const float Tn2  = __shfl_down_sync(m, T,  2);
    const float p3n2 = __shfl_down_sync(m, p3, 2);
    const float p1n3 = __shfl_down_sync(m, v0, 3);
    const float p2n3 = __shfl_down_sync(m, p2, 3);
    const float TT = Tn1 + Tn2;
    W0 = T + Tn1 + p3n2;
    W1 = suf1 + TT;
    W2 = (suf2 + p1n3) + TT;
    W3 = (v3 + p2n3) + TT;
}

__global__ __launch_bounds__(128) void ssim_main(
    const float* __restrict__ img1, const float* __restrict__ img2,
    float* __restrict__ out)
{
    const int wib  = threadIdx.x >> 5;
    const int w    = blockIdx.x * WARPS_PER_BLOCK + wib;
    const int lane = threadIdx.x & 31;
    const int tid  = threadIdx.x;

    const int g     = w % NGROUPS;
    const int t     = w / NGROUPS;
    const int img   = t & 15;
    const int strip = t >> 4;

    const int gb = g * GROUP_W;          // first output col of this group
    const int m0 = 4 * lane;             // lane's first ext index

    // Load validity per element k: ext col = gb-5+m0+k must be in [0, 504)
    bool ok[4];
    #pragma unroll
    for (int k = 0; k < 4; ++k) {
        const int ec = gb - 5 + m0 + k;
        ok[k] = ((unsigned)ec < (unsigned)OUTW);
    }
    // Output validity per k
    bool ov[4];
    #pragma unroll
    for (int k = 0; k < 4; ++k) {
        const int mp = m0 + k;
        ov[k] = (mp <= 117) && (gb + mp < OUTW);
    }

    // Base pointers: global col = (ext col) + CROPV = gb - 1 + m0 (+k)
    const float* p1 = img1 + (long)img * IMG_STRIDE + (gb - 1 + m0);
    const float* p2 = img2 + (long)img * IMG_STRIDE + (gb - 1 + m0);

    const int r0 = strip * STRIP_H;
    const int rmin = (r0 - 5 > 0) ? r0 - 5 : 0;   // first row ever admitted

    float V1[4], V2[4], Vss[4], V12[4];
    #pragma unroll
    for (int k = 0; k < 4; ++k) { V1[k] = 0.f; V2[k] = 0.f; Vss[k] = 0.f; V12[k] = 0.f; }
    float acc = 0.f;

    const float C1 = 6.5025f;      // (0.01*255)^2
    const float C2 = 58.5225f;     // (0.03*255)^2
    const float K  = 1.0f / 121.0f;

    // Prologue: admit rows r0-5 .. r0+4 (zero padding for r < 0).
    #pragma unroll
    for (int j = 0; j < 10; ++j) {
        const int r = r0 - 5 + j;
        if (r >= 0) {
            const float* r1 = p1 + (long)(r + CROPV) * W_IN;
            const float* r2 = p2 + (long)(r + CROPV) * W_IN;
            #pragma unroll
            for (int k = 0; k < 4; ++k) {
                const float a = ok[k] ? __ldg(r1 + k) : 0.f;
                const float b = ok[k] ? __ldg(r2 + k) : 0.f;
                V1[k] += a; V2[k] += b;
                Vss[k] = fmaf(a, a, Vss[k]); Vss[k] = fmaf(b, b, Vss[k]);
                V12[k] = fmaf(a, b, V12[k]);
            }
        }
    }

    // Main loop over output rows.
    for (int y = r0; y < r0 + STRIP_H; ++y) {
        // Retire row y-6 (only if it was ever admitted).
        const int ro = y - 6;
        if (ro >= rmin) {
            const float* r1 = p1 + (long)(ro + CROPV) * W_IN;
            const float* r2 = p2 + (long)(ro + CROPV) * W_IN;
            #pragma unroll
            for (int k = 0; k < 4; ++k) {
                const float a = ok[k] ? __ldg(r1 + k) : 0.f;   // L1 hit
                const float b = ok[k] ? __ldg(r2 + k) : 0.f;
                V1[k] -= a; V2[k] -= b;
                Vss[k] = fmaf(-a, a, Vss[k]); Vss[k] = fmaf(-b, b, Vss[k]);
                V12[k] = fmaf(-a, b, V12[k]);
            }
        }
        // Admit row y+5 (zero padding beyond 503).
        const int rn = y + 5;
        if (rn < OUTW) {
            const float* r1 = p1 + (long)(rn + CROPV) * W_IN;
            const float* r2 = p2 + (long)(rn + CROPV) * W_IN;
            #pragma unroll
            for (int k = 0; k < 4; ++k) {
                const float a = ok[k] ? __ldg(r1 + k) : 0.f;
                const float b = ok[k] ? __ldg(r2 + k) : 0.f;
                V1[k] += a; V2[k] += b;
                Vss[k] = fmaf(a, a, Vss[k]); Vss[k] = fmaf(b, b, Vss[k]);
                V12[k] = fmaf(a, b, V12[k]);
            }
        }

        // Horizontal windows (4 quantities, shallow independent shfl chains).
        float B1[4], B2[4], Bss[4], B12[4];
        win4(V1[0],  V1[1],  V1[2],  V1[3],  B1[0],  B1[1],  B1[2],  B1[3]);
        win4(V2[0],  V2[1],  V2[2],  V2[3],  B2[0],  B2[1],  B2[2],  B2[3]);
        win4(Vss[0], Vss[1], Vss[2], Vss[3], Bss[0], Bss[1], Bss[2], Bss[3]);
        win4(V12[0], V12[1], V12[2], V12[3], B12[0], B12[1], B12[2], B12[3]);

        #pragma unroll
        for (int k = 0; k < 4; ++k) {
            if (ov[k]) {
                const float mu1  = B1[k] * K;
                const float mu2  = B2[k] * K;
                const float mu12 = mu1 * mu2;
                const float musq = fmaf(mu1, mu1, mu2 * mu2);
                const float s12  = fmaf(B12[k], K, -mu12);   // sigma12
                const float sss  = fmaf(Bss[k], K, -musq);   // sigma1^2+sigma2^2
                const float num  = fmaf(2.f, mu12, C1) * fmaf(2.f, s12, C2);
                const float den  = (musq + C1) * (sss + C2);
                acc += __fdividef(num, den);
            }
        }
    }

    // ---- block partial + fused final reduction ----
    #pragma unroll
    for (int d = 16; d; d >>= 1)
        acc += __shfl_xor_sync(0xffffffffu, acc, d);

    __shared__ float sp[WARPS_PER_BLOCK];
    __shared__ int   isLast;
    if (lane == 0) sp[wib] = acc;
    __syncthreads();
    if (tid == 0) {
        float s = sp[0] + sp[1] + sp[2] + sp[3];
        g_partials[blockIdx.x] = s;
        __threadfence();
        const int c = atomicAdd(&g_count, 1);
        isLast = (c == NBLOCKS - 1);
    }
    __syncthreads();

    if (isLast) {
        // Deterministic: fixed index order per thread, fixed tree reduce.
        float v = 0.f;
        for (int i = tid; i < NBLOCKS; i += 128)
            v += __ldcg(&g_partials[i]);
        #pragma unroll
        for (int d = 16; d; d >>= 1)
            v += __shfl_xor_sync(0xffffffffu, v, d);
        if (lane == 0) sp[wib] = v;
        __syncthreads();
        if (tid == 0) {
            const float total = sp[0] + sp[1] + sp[2] + sp[3];
            out[0] = total * (1.0f / 4064256.0f);   // 16*504*504
            g_count = 0;                             // reset for next replay
        }
    }
}

extern "C" void kernel_launch(void* const* d_in, const int* in_sizes, int n_in,
                              void* d_out, int out_size)
{
    const float* img1 = (const float*)d_in[0];
    const float* img2 = (const float*)d_in[1];
    float* out = (float*)d_out;
    ssim_main<<<NBLOCKS, 128>>>(img1, img2, out);
}

// round 11
// speedup vs baseline: 1.8649x; 1.3361x over previous
#include <cuda_runtime.h>

// SSIM, fused single-pass box filters, 4 cols/lane, aligned float4 loads,
// software-prefetched vertical updates.
//
// img (16,3,512,512) f32; channel 0, crop 4 -> 504x504.
// Groups: ext base e0 = 116g-8 (16B-aligned quads per lane); each warp holds
// 128 ext cols, computes 118 windows; per-element ov ranges partition [0,504).
// Vertical 11-row running sums; per iteration: issue admit/retire loads FIRST,
// then win4 (5 shfl / 4 outputs) + SSIM on current state, then apply updates
// (~150-instr slack hides L2 latency).
// 5 groups x 16 images x 36 strips(14 rows) = 2880 warps -> 720 blocks x 128.

#define IMG_STRIDE (3 * 512 * 512)
#define W4 128            // float4 per image row (512 floats)
#define OUTW 504
#define NGROUPS 5
#define STRIPS 36
#define STRIP_H 14        // 36*14 = 504
#define NWARPS (NGROUPS * 16 * STRIPS)      // 2880
#define WPB 4
#define NBLOCKS (NWARPS / WPB)              // 720

__device__ float g_partials[NBLOCKS];
__device__ int   g_count = 0;

// Horizontal 11-window: lane L holds ext elems m=4L..4L+3 (v0..v3).
// W[k] = sum over ext m'=4L+k .. m'+10.
__device__ __forceinline__ void win4(float v0, float v1, float v2, float v3,
                                     float& W0, float& W1, float& W2, float& W3)
{
    const unsigned m = 0xffffffffu;
    const float p2 = v0 + v1;
    const float p3 = p2 + v2;
    const float T  = p3 + v3;
    const float suf1 = T - v0;
    const float suf2 = v2 + v3;
    const float Tn1  = __shfl_down_sync(m, T,  1);
    const float Tn2  = __shfl_down_sync(m, T,  2);
    const float p3n2 = __shfl_down_sync(m, p3, 2);
    const float p1n3 = __shfl_down_sync(m, v0, 3);
    const float p2n3 = __shfl_down_sync(m, p2, 3);
    const float TT = Tn1 + Tn2;
    W0 = T + Tn1 + p3n2;
    W1 = suf1 + TT;
    W2 = (suf2 + p1n3) + TT;
    W3 = (v3 + p2n3) + TT;
}

#define ADMIT(k, av, bv)                                     \
    V1[k] += (av); V2[k] += (bv);                            \
    Vss[k] = fmaf((av), (av), Vss[k]);                       \
    Vss[k] = fmaf((bv), (bv), Vss[k]);                       \
    V12[k] = fmaf((av), (bv), V12[k]);

#define UPDATE(k, an, bn, ao, bo)                            \
    V1[k] += (an) - (ao); V2[k] += (bn) - (bo);              \
    Vss[k] = fmaf((an), (an), Vss[k]);                       \
    Vss[k] = fmaf((bn), (bn), Vss[k]);                       \
    Vss[k] = fmaf(-(ao), (ao), Vss[k]);                      \
    Vss[k] = fmaf(-(bo), (bo), Vss[k]);                      \
    V12[k] = fmaf((an), (bn), V12[k]);                       \
    V12[k] = fmaf(-(ao), (bo), V12[k]);

__global__ __launch_bounds__(128) void ssim_main(
    const float* __restrict__ img1, const float* __restrict__ img2,
    float* __restrict__ out)
{
    const int wib  = threadIdx.x >> 5;
    const int w    = blockIdx.x * WPB + wib;
    const int lane = threadIdx.x & 31;
    const int tid  = threadIdx.x;

    const int g     = w % NGROUPS;
    const int t     = w / NGROUPS;
    const int img   = t & 15;
    const int strip = t >> 4;

    // Aligned ext base; output range partition.
    const int e0 = 116 * g - 8;
    const int lo = (g == 0) ? 0    : (116 * g - 3);
    const int hi = (g == 4) ? OUTW : (116 * g + 113);

    const int ec = e0 + 4 * lane;                  // lane's quad ext start
    const bool loadok = (ec >= 0) && (ec <= 500);  // whole quad in [0,504)

    bool ov[4];
    #pragma unroll
    for (int k = 0; k < 4; ++k) {
        const int c = ec + 5 + k;                  // output col of W[k]
        ov[k] = (c >= lo) && (c < hi);
    }

    // Quad pointers: global col = ec + 4 (aligned); row r at +(r+4)*W4.
    const float4* q1 = reinterpret_cast<const float4*>(
        img1 + (size_t)img * IMG_STRIDE) + ((ec >> 2) + 1);
    const float4* q2 = reinterpret_cast<const float4*>(
        img2 + (size_t)img * IMG_STRIDE) + ((ec >> 2) + 1);

    const int r0 = strip * STRIP_H;

    float V1[4]  = {0.f, 0.f, 0.f, 0.f};
    float V2[4]  = {0.f, 0.f, 0.f, 0.f};
    float Vss[4] = {0.f, 0.f, 0.f, 0.f};
    float V12[4] = {0.f, 0.f, 0.f, 0.f};

    // Prologue: V = rows r0-5 .. r0+5 (zero-padded below 0).
    {
        const float4* pP1 = q1 + (ptrdiff_t)(r0 - 1) * W4;   // row r0-5
        const float4* pP2 = q2 + (ptrdiff_t)(r0 - 1) * W4;
        #pragma unroll
        for (int j = 0; j < 11; ++j) {
            const int r = r0 - 5 + j;
            float4 a = {0.f,0.f,0.f,0.f}, b = {0.f,0.f,0.f,0.f};
            if (loadok && r >= 0) { a = __ldg(pP1); b = __ldg(pP2); }
            pP1 += W4; pP2 += W4;
            ADMIT(0, a.x, b.x) ADMIT(1, a.y, b.y)
            ADMIT(2, a.z, b.z) ADMIT(3, a.w, b.w)
        }
    }

    const float C1K = 6.5025f  * 14641.f;   // C1 * 121^2
    const float C2K = 58.5225f * 14641.f;   // C2 * 121^2
    float acc = 0.f;

    const float4* pA1 = q1 + (ptrdiff_t)(r0 + 10) * W4;  // admit row r0+6
    const float4* pA2 = q2 + (ptrdiff_t)(r0 + 10) * W4;
    const float4* pR1 = q1 + (ptrdiff_t)(r0 - 1)  * W4;  // retire row r0-5
    const float4* pR2 = q2 + (ptrdiff_t)(r0 - 1)  * W4;

    #pragma unroll 2
    for (int i = 0; i < STRIP_H; ++i) {
        const int y = r0 + i;

        // Issue next-state loads FIRST (consumed ~150 instrs later).
        float4 na = {0.f,0.f,0.f,0.f}, nb = {0.f,0.f,0.f,0.f};
        float4 oa = {0.f,0.f,0.f,0.f}, ob = {0.f,0.f,0.f,0.f};
        if (loadok && y <= OUTW - 7) { na = __ldg(pA1); nb = __ldg(pA2); }
        if (loadok && y >= 5)        { oa = __ldg(pR1); ob = __ldg(pR2); }
        pA1 += W4; pA2 += W4; pR1 += W4; pR2 += W4;

        // Horizontal windows on CURRENT vertical state (no dep on loads).
        float B1[4], B2[4], Bss[4], B12[4];
        win4(V1[0],  V1[1],  V1[2],  V1[3],  B1[0],  B1[1],  B1[2],  B1[3]);
        win4(V2[0],  V2[1],  V2[2],  V2[3],  B2[0],  B2[1],  B2[2],  B2[3]);
        win4(Vss[0], Vss[1], Vss[2], Vss[3], Bss[0], Bss[1], Bss[2], Bss[3]);
        win4(V12[0], V12[1], V12[2], V12[3], B12[0], B12[1], B12[2], B12[3]);

        // SSIM in 121-scaled domain (num/den both scaled by 121^4).
        #pragma unroll
        for (int k = 0; k < 4; ++k) {
            const float P   = B1[k] * B2[k];
            const float Q   = fmaf(B1[k], B1[k], B2[k] * B2[k]);
            const float t12 = fmaf(121.f, B12[k], -P);
            const float tss = fmaf(121.f, Bss[k], -Q);
            const float num = fmaf(2.f, P, C1K) * fmaf(2.f, t12, C2K);
            const float den = (Q + C1K) * (tss + C2K);
            const float r   = __fdividef(num, den);
            if (ov[k]) acc += r;
        }

        // Apply vertical update: V(y) -> V(y+1).
        UPDATE(0, na.x, nb.x, oa.x, ob.x)
        UPDATE(1, na.y, nb.y, oa.y, ob.y)
        UPDATE(2, na.z, nb.z, oa.z, ob.z)
        UPDATE(3, na.w, nb.w, oa.w, ob.w)
    }

    // ---- block partial + fused final reduction ----
    #pragma unroll
    for (int d = 16; d; d >>= 1)
        acc += __shfl_xor_sync(0xffffffffu, acc, d);

    __shared__ float sp[WPB];
    __shared__ int   isLast;
    if (lane == 0) sp[wib] = acc;
    __syncthreads();
    if (tid == 0) {
        g_partials[blockIdx.x] = sp[0] + sp[1] + sp[2] + sp[3];
        __threadfence();
        isLast = (atomicAdd(&g_count, 1) == NBLOCKS - 1);
    }
    __syncthreads();

    if (isLast) {
        float v = 0.f;
        for (int i = tid; i < NBLOCKS; i += 128)
            v += __ldcg(&g_partials[i]);
        #pragma unroll
        for (int d = 16; d; d >>= 1)
            v += __shfl_xor_sync(0xffffffffu, v, d);
        if (lane == 0) sp[wib] = v;
        __syncthreads();
        if (tid == 0) {
            out[0] = (sp[0] + sp[1] + sp[2] + sp[3]) * (1.0f / 4064256.0f);
            g_count = 0;   // reset for next graph replay
        }
    }
}

extern "C" void kernel_launch(void* const* d_in, const int* in_sizes, int n_in,
                              void* d_out, int out_size)
{
    const float* img1 = (const float*)d_in[0];
    const float* img2 = (const float*)d_in[1];
    float* out = (float*)d_out;
    ssim_main<<<NBLOCKS, 128>>>(img1, img2, out);
}